// round 1
// baseline (speedup 1.0000x reference)
#include <cuda_runtime.h>
#include <cuda_bf16.h>

// Problem constants (fixed by the reference):
// B=16, T=4096, L=4, H=W=128, D=32, MAX_DIM=0.55
#define NB 16
#define NT 4096
#define NPTS (NB * NT)
#define MAXDIM 0.55f

__global__ __launch_bounds__(256)
void decoder_kernel(const float* __restrict__ p,
                    const float* __restrict__ c,
                    const float* __restrict__ C_mat,
                    const float* __restrict__ fc_p_W,
                    const float* __restrict__ fc_p_b,
                    const float* __restrict__ W0,
                    const float* __restrict__ b0,
                    const float* __restrict__ W1,
                    const float* __restrict__ b1,
                    const float* __restrict__ foW,
                    const float* __restrict__ fob,
                    float* __restrict__ out)
{
    // Transposed weight staging: s[i][j][k] = W[i][k][j] so the k-reduction
    // is contiguous (LDS.128-friendly, broadcast across the warp).
    __shared__ float sW0[5][32][32];
    __shared__ float sW1[5][32][32];
    __shared__ float sb0[5][32];
    __shared__ float sb1[5][32];
    __shared__ float sfp[3][32];
    __shared__ float sfpb[32];
    __shared__ float sfo[32];
    __shared__ float sfob;

    const int tid = threadIdx.x;
    for (int idx = tid; idx < 5 * 32 * 32; idx += 256) {
        int i = idx >> 10;
        int rem = idx & 1023;
        int k = rem >> 5;
        int j = rem & 31;
        sW0[i][j][k] = W0[idx];
        sW1[i][j][k] = W1[idx];
    }
    for (int idx = tid; idx < 5 * 32; idx += 256) {
        sb0[idx >> 5][idx & 31] = b0[idx];
        sb1[idx >> 5][idx & 31] = b1[idx];
    }
    if (tid < 96) sfp[tid >> 5][tid & 31] = fc_p_W[tid];
    if (tid < 32) { sfpb[tid] = fc_p_b[tid]; sfo[tid] = foW[tid]; }
    if (tid == 0) sfob = fob[0];
    __syncthreads();

    const int gid = blockIdx.x * 256 + tid;
    if (gid >= NPTS) return;
    const int b = gid >> 12;  // gid / 4096

    const float px = p[gid * 3 + 0];
    const float py = p[gid * 3 + 1];
    const float pz = p[gid * 3 + 2];
    const float qx = px / MAXDIM, qy = py / MAXDIM, qz = pz / MAXDIM;

    // ---- bilinear gather over 4 views, accumulated into cf[32] ----
    float cf[32];
#pragma unroll
    for (int d = 0; d < 32; d++) cf[d] = 0.0f;

    const float interval = 2.0f / 127.0f;

#pragma unroll
    for (int l = 0; l < 4; l++) {
        const float* Cm = C_mat + ((b * 4 + l) * 4) * 3;
        float pr0 = Cm[0] * qx + Cm[1] * qy + Cm[2] * qz;
        float pr1 = Cm[3] * qx + Cm[4] * qy + Cm[5] * qz;
        const float denom = Cm[9] + 0.05f;  // C_mat[b,l,3,0] + 0.05
        pr0 = pr0 / denom;
        pr1 = pr1 / denom;
        float xg = (pr0 + 1.0f) / interval;
        float yg = (pr1 + 1.0f) / interval;
        // clamp exactly like the reference
        if (xg >= 127.0f) xg = 126.9f;
        if (xg < 0.0f)    xg = 0.0f;
        if (yg >= 127.0f) yg = 126.9f;
        if (yg < 0.0f)    yg = 0.0f;
        // round half-to-even (matches jnp.round / torch.round)
        const float xl = rintf(xg - 0.5f);
        const float xr = rintf(xg + 0.5f);
        const float yl = rintf(yg - 0.5f);
        const float yh = rintf(yg + 0.5f);
        const int xi_l = (int)xl, xi_r = (int)xr;
        const int yi_l = (int)yl, yi_h = (int)yh;
        const float dx = xr - xg;
        const float dy = yh - yg;
        const float w11 = dx * dy;
        const float w12 = (1.0f - dx) * dy;
        const float w21 = dx * (1.0f - dy);
        const float w22 = (1.0f - dx) * (1.0f - dy);

        const float* base = c + (size_t)(b * 4 + l) * (128 * 128 * 32);
        const float4* f11 = (const float4*)(base + (xi_l * 128 + yi_l) * 32);
        const float4* f12 = (const float4*)(base + (xi_r * 128 + yi_l) * 32);
        const float4* f21 = (const float4*)(base + (xi_l * 128 + yi_h) * 32);
        const float4* f22 = (const float4*)(base + (xi_r * 128 + yi_h) * 32);

#pragma unroll
        for (int v = 0; v < 8; v++) {
            const float4 a  = f11[v];
            const float4 bb = f12[v];
            const float4 cc = f21[v];
            const float4 dd = f22[v];
            cf[v * 4 + 0] += a.x * w11 + bb.x * w12 + cc.x * w21 + dd.x * w22;
            cf[v * 4 + 1] += a.y * w11 + bb.y * w12 + cc.y * w21 + dd.y * w22;
            cf[v * 4 + 2] += a.z * w11 + bb.z * w12 + cc.z * w21 + dd.z * w22;
            cf[v * 4 + 3] += a.w * w11 + bb.w * w12 + cc.w * w21 + dd.w * w22;
        }
    }

    // ---- net = fc_p(p) ----
    float net[32];
#pragma unroll
    for (int j = 0; j < 32; j++) {
        net[j] = sfpb[j] + px * sfp[0][j] + py * sfp[1][j] + pz * sfp[2][j];
    }

    // ---- 5 ResnetBlockFC blocks, cf added before each ----
    float h[32];
    float r[32];
    for (int i = 0; i < 5; i++) {
#pragma unroll
        for (int j = 0; j < 32; j++) net[j] += cf[j];
#pragma unroll
        for (int k = 0; k < 32; k++) r[k] = fmaxf(net[k], 0.0f);
#pragma unroll 4
        for (int j = 0; j < 32; j++) {
            float acc = sb0[i][j];
            const float* w = &sW0[i][j][0];
#pragma unroll
            for (int k = 0; k < 32; k++) acc += r[k] * w[k];
            h[j] = fmaxf(acc, 0.0f);  // relu(fc_0 output)
        }
#pragma unroll 4
        for (int j = 0; j < 32; j++) {
            float acc = sb1[i][j];
            const float* w = &sW1[i][j][0];
#pragma unroll
            for (int k = 0; k < 32; k++) acc += h[k] * w[k];
            net[j] += acc;  // residual add
        }
    }

    // ---- out = relu(net) @ fc_out_W + fc_out_b ----
    float acc = sfob;
#pragma unroll
    for (int k = 0; k < 32; k++) acc += fmaxf(net[k], 0.0f) * sfo[k];
    out[gid] = acc;
}

extern "C" void kernel_launch(void* const* d_in, const int* in_sizes, int n_in,
                              void* d_out, int out_size) {
    // metadata order:
    // 0:p 1:z 2:c 3:C_mat 4:fc_p_W 5:fc_p_b 6:blocks_W0 7:blocks_b0
    // 8:blocks_W1 9:blocks_b1 10:fc_out_W 11:fc_out_b
    const float* p      = (const float*)d_in[0];
    const float* c      = (const float*)d_in[2];
    const float* C_mat  = (const float*)d_in[3];
    const float* fc_p_W = (const float*)d_in[4];
    const float* fc_p_b = (const float*)d_in[5];
    const float* W0     = (const float*)d_in[6];
    const float* b0     = (const float*)d_in[7];
    const float* W1     = (const float*)d_in[8];
    const float* b1     = (const float*)d_in[9];
    const float* foW    = (const float*)d_in[10];
    const float* fob    = (const float*)d_in[11];
    float* out = (float*)d_out;

    const int threads = 256;
    const int blocks = (NPTS + threads - 1) / threads;
    decoder_kernel<<<blocks, threads>>>(p, c, C_mat, fc_p_W, fc_p_b,
                                        W0, b0, W1, b1, foW, fob, out);
}

// round 2
// speedup vs baseline: 1.5803x; 1.5803x over previous
#include <cuda_runtime.h>
#include <cuda_bf16.h>

// Problem constants (fixed by the reference):
// B=16, T=4096, L=4, H=W=128, D=32, MAX_DIM=0.55
#define NB 16
#define NT 4096
#define NPTS (NB * NT)
#define MAXDIM 0.55f

// Dynamic shared memory layout (float offsets)
#define OFF_W0   0            // 5*32*32 = 5120, raw layout [i][k][j]
#define OFF_W1   5120         // 5120
#define OFF_B0   10240        // 160
#define OFF_B1   10400        // 160
#define OFF_FP   10560        // 96  fc_p_W [3][32]
#define OFF_FPB  10656        // 32
#define OFF_FO   10688        // 32
#define OFF_FOB  10720        // 1  (pad to 10752)
#define OFF_PW   10752        // 256*32 = 8192 (per-thread: 16 int offs + 16 float wts)
#define OFF_CF   (10752+8192) // 256*33 = 8448 (padded cf tile)
#define SMEM_FLOATS (OFF_CF + 256*33)
#define SMEM_BYTES  (SMEM_FLOATS * 4)

typedef unsigned long long u64;

__device__ __forceinline__ u64 pack2(float lo, float hi) {
    u64 r; asm("mov.b64 %0, {%1,%2};" : "=l"(r) : "f"(lo), "f"(hi)); return r;
}
__device__ __forceinline__ void unpack2(u64 v, float& lo, float& hi) {
    asm("mov.b64 {%0,%1}, %2;" : "=f"(lo), "=f"(hi) : "l"(v));
}
__device__ __forceinline__ u64 fma2(u64 a, u64 b, u64 c) {
    u64 d; asm("fma.rn.f32x2 %0, %1, %2, %3;" : "=l"(d) : "l"(a), "l"(b), "l"(c)); return d;
}

__global__ __launch_bounds__(256, 2)
void decoder_kernel(const float* __restrict__ p,
                    const float* __restrict__ c,
                    const float* __restrict__ C_mat,
                    const float* __restrict__ fc_p_W,
                    const float* __restrict__ fc_p_b,
                    const float* __restrict__ W0,
                    const float* __restrict__ b0,
                    const float* __restrict__ W1,
                    const float* __restrict__ b1,
                    const float* __restrict__ foW,
                    const float* __restrict__ fob,
                    float* __restrict__ out)
{
    extern __shared__ float sm[];
    const int tid = threadIdx.x;

    // ---- stage all weights (raw layout, j contiguous for f32x2 pairs) ----
    {
        const float4* s0 = (const float4*)W0;
        const float4* s1 = (const float4*)W1;
        float4* d0 = (float4*)(sm + OFF_W0);
        float4* d1 = (float4*)(sm + OFF_W1);
        for (int i = tid; i < 1280; i += 256) { d0[i] = s0[i]; d1[i] = s1[i]; }
        if (tid < 160) { sm[OFF_B0 + tid] = b0[tid]; sm[OFF_B1 + tid] = b1[tid]; }
        if (tid < 96)  sm[OFF_FP + tid] = fc_p_W[tid];
        if (tid < 32)  { sm[OFF_FPB + tid] = fc_p_b[tid]; sm[OFF_FO + tid] = foW[tid]; }
        if (tid == 0)  sm[OFF_FOB] = fob[0];
    }
    __syncthreads();

    const int gid   = blockIdx.x * 256 + tid;
    const int b     = gid >> 12;       // all threads in a warp share b (4096 | 32)
    const int lane  = tid & 31;
    const int wbase = tid & ~31;

    const float px = p[gid * 3 + 0];
    const float py = p[gid * 3 + 1];
    const float pz = p[gid * 3 + 2];
    const float qx = px / MAXDIM, qy = py / MAXDIM, qz = pz / MAXDIM;

    // ---- per-lane precompute: 4 views -> (4 corner offsets, 4 weights) each ----
    float* myPW = sm + OFF_PW + tid * 32;
    {
        const float interval = 2.0f / 127.0f;
#pragma unroll
        for (int l = 0; l < 4; l++) {
            const float* Cm = C_mat + ((b * 4 + l) * 4) * 3;
            float pr0 = Cm[0] * qx + Cm[1] * qy + Cm[2] * qz;
            float pr1 = Cm[3] * qx + Cm[4] * qy + Cm[5] * qz;
            const float denom = Cm[9] + 0.05f;
            pr0 /= denom; pr1 /= denom;
            float xg = (pr0 + 1.0f) / interval;
            float yg = (pr1 + 1.0f) / interval;
            if (xg >= 127.0f) xg = 126.9f;
            if (xg < 0.0f)    xg = 0.0f;
            if (yg >= 127.0f) yg = 126.9f;
            if (yg < 0.0f)    yg = 0.0f;
            const float xl = rintf(xg - 0.5f);
            const float xr = rintf(xg + 0.5f);
            const float yl = rintf(yg - 0.5f);
            const float yh = rintf(yg + 0.5f);
            const int xi_l = (int)xl, xi_r = (int)xr;
            const int yi_l = (int)yl, yi_h = (int)yh;
            const float dx = xr - xg;
            const float dy = yh - yg;
            const int vb = (b * 4 + l) * (128 * 128 * 32);
            ((int4*)myPW)[l] = make_int4(vb + (xi_l * 128 + yi_l) * 32,
                                         vb + (xi_r * 128 + yi_l) * 32,
                                         vb + (xi_l * 128 + yi_h) * 32,
                                         vb + (xi_r * 128 + yi_h) * 32);
            ((float4*)(myPW + 16))[l] = make_float4(dx * dy,
                                                    (1.0f - dx) * dy,
                                                    dx * (1.0f - dy),
                                                    (1.0f - dx) * (1.0f - dy));
        }
    }
    __syncwarp();

    // ---- warp-cooperative gather: lane = channel, loop over warp's 32 points ----
    {
        const float* pwW = sm + OFF_PW + wbase * 32;
        float*       cfW = sm + OFF_CF + wbase * 33;
#pragma unroll 2
        for (int t = 0; t < 32; t++) {
            const float* pwt = pwW + t * 32;
            float acc = 0.0f;
#pragma unroll
            for (int l = 0; l < 4; l++) {
                const int4   o = ((const int4*)pwt)[l];          // broadcast LDS.128
                const float4 w = ((const float4*)(pwt + 16))[l]; // broadcast LDS.128
                const float f11 = c[o.x + lane];  // coalesced: exactly one 128B line
                const float f12 = c[o.y + lane];
                const float f21 = c[o.z + lane];
                const float f22 = c[o.w + lane];
                acc += w.x * f11 + w.y * f12 + w.z * f21 + w.w * f22;
            }
            cfW[t * 33 + lane] = acc;   // stride 33: conflict-free
        }
    }
    __syncwarp();

    const float* cf = sm + OFF_CF + tid * 33;

    // ---- net = fc_p(p) ----
    float net[32];
#pragma unroll
    for (int j = 0; j < 32; j++) {
        net[j] = sm[OFF_FPB + j] + px * sm[OFF_FP + j]
               + py * sm[OFF_FP + 32 + j] + pz * sm[OFF_FP + 64 + j];
    }

    // ---- 5 ResnetBlockFC blocks (f32x2 packed matmuls), cf added before each ----
#pragma unroll 1
    for (int i = 0; i < 5; i++) {
        const float* Wr0 = sm + OFF_W0 + i * 1024;
        const float* Wr1 = sm + OFF_W1 + i * 1024;

#pragma unroll
        for (int j = 0; j < 32; j++) net[j] += cf[j];

        // fc_0: acc[j] = b0 + sum_k relu(net[k]) * W0[k][j]
        u64 acc[16];
        {
            const ulonglong2* bp = (const ulonglong2*)(sm + OFF_B0 + i * 32);
#pragma unroll
            for (int q = 0; q < 8; q++) { ulonglong2 v = bp[q]; acc[2*q] = v.x; acc[2*q+1] = v.y; }
        }
#pragma unroll
        for (int k = 0; k < 32; k++) {
            const float rv = fmaxf(net[k], 0.0f);
            const u64 rk2 = pack2(rv, rv);
            const ulonglong2* wr = (const ulonglong2*)(Wr0 + k * 32);
#pragma unroll
            for (int q = 0; q < 8; q++) {
                ulonglong2 w = wr[q];
                acc[2*q]   = fma2(rk2, w.x, acc[2*q]);
                acc[2*q+1] = fma2(rk2, w.y, acc[2*q+1]);
            }
        }
        // h = relu(fc_0 out)
        float h[32];
#pragma unroll
        for (int q = 0; q < 16; q++) {
            float lo, hi; unpack2(acc[q], lo, hi);
            h[2*q] = fmaxf(lo, 0.0f); h[2*q+1] = fmaxf(hi, 0.0f);
        }
        // fc_1: a2[j] = b1 + sum_k h[k] * W1[k][j]
        u64 a2[16];
        {
            const ulonglong2* bp = (const ulonglong2*)(sm + OFF_B1 + i * 32);
#pragma unroll
            for (int q = 0; q < 8; q++) { ulonglong2 v = bp[q]; a2[2*q] = v.x; a2[2*q+1] = v.y; }
        }
#pragma unroll
        for (int k = 0; k < 32; k++) {
            const u64 rk2 = pack2(h[k], h[k]);
            const ulonglong2* wr = (const ulonglong2*)(Wr1 + k * 32);
#pragma unroll
            for (int q = 0; q < 8; q++) {
                ulonglong2 w = wr[q];
                a2[2*q]   = fma2(rk2, w.x, a2[2*q]);
                a2[2*q+1] = fma2(rk2, w.y, a2[2*q+1]);
            }
        }
        // residual add
#pragma unroll
        for (int q = 0; q < 16; q++) {
            float lo, hi; unpack2(a2[q], lo, hi);
            net[2*q] += lo; net[2*q+1] += hi;
        }
    }

    // ---- out = relu(net) @ fc_out_W + fc_out_b ----
    float o = sm[OFF_FOB];
#pragma unroll
    for (int k = 0; k < 32; k++) o += fmaxf(net[k], 0.0f) * sm[OFF_FO + k];
    out[gid] = o;
}

extern "C" void kernel_launch(void* const* d_in, const int* in_sizes, int n_in,
                              void* d_out, int out_size) {
    // metadata order:
    // 0:p 1:z 2:c 3:C_mat 4:fc_p_W 5:fc_p_b 6:blocks_W0 7:blocks_b0
    // 8:blocks_W1 9:blocks_b1 10:fc_out_W 11:fc_out_b   (z unused by reference)
    const float* p      = (const float*)d_in[0];
    const float* c      = (const float*)d_in[2];
    const float* C_mat  = (const float*)d_in[3];
    const float* fc_p_W = (const float*)d_in[4];
    const float* fc_p_b = (const float*)d_in[5];
    const float* W0     = (const float*)d_in[6];
    const float* b0     = (const float*)d_in[7];
    const float* W1     = (const float*)d_in[8];
    const float* b1     = (const float*)d_in[9];
    const float* foW    = (const float*)d_in[10];
    const float* fob    = (const float*)d_in[11];
    float* out = (float*)d_out;

    cudaFuncSetAttribute(decoder_kernel,
                         cudaFuncAttributeMaxDynamicSharedMemorySize, SMEM_BYTES);

    const int threads = 256;
    const int blocks = NPTS / threads;  // 256
    decoder_kernel<<<blocks, threads, SMEM_BYTES>>>(p, c, C_mat, fc_p_W, fc_p_b,
                                                    W0, b0, W1, b1, foW, fob, out);
}